// round 3
// baseline (speedup 1.0000x reference)
#include <cuda_runtime.h>
#include <cuda_bf16.h>
#include <cstdint>

// Problem constants (match reference_code)
#define IN_C    128
#define HID_C   256
#define OUT_C   128
#define N_NODES 50000
#define N_EDGES 600000

// ---------------------------------------------------------------------------
// Scratch (no cudaMalloc allowed): device globals
// ---------------------------------------------------------------------------
__device__ float g_agg1[(size_t)N_NODES * IN_C];   // 25.6 MB  sum of x over in-edges
__device__ float g_agg2[(size_t)N_NODES * HID_C];  // 51.2 MB  sum of h over in-edges
__device__ float g_h   [(size_t)N_NODES * HID_C];  // 51.2 MB  layer-1 output
__device__ float g_cnt [N_NODES];                  // in-degree (float)
__device__ float g_inv [N_NODES];                  // 1 / max(cnt, 1)

// ---------------------------------------------------------------------------
// Zeroing kernel (pure kernel node, capture-safe)
// ---------------------------------------------------------------------------
__global__ void zero_kernel(float4* __restrict__ p, int n4)
{
    int i = blockIdx.x * blockDim.x + threadIdx.x;
    int stride = gridDim.x * blockDim.x;
    float4 z = make_float4(0.f, 0.f, 0.f, 0.f);
    for (; i < n4; i += stride) p[i] = z;
}

// ---------------------------------------------------------------------------
// Scatter-add: one warp per edge, float4 gather + scalar atomicAdd (REDG).
// edge_index is int32 (JAX default config downgrades int64 -> int32).
// ---------------------------------------------------------------------------
template<int C, bool COUNT>
__global__ void scatter_kernel(const float* __restrict__ feat,
                               const int* __restrict__ src,
                               const int* __restrict__ dst,
                               float* __restrict__ agg)
{
    int e = blockIdx.x * (blockDim.x >> 5) + (threadIdx.x >> 5);
    if (e >= N_EDGES) return;
    int lane = threadIdx.x & 31;
    int s = src[e];
    int d = dst[e];
    const float4* f = (const float4*)(feat + (size_t)s * C);
    float*        o = agg + (size_t)d * C;
    #pragma unroll
    for (int i = lane; i < C / 4; i += 32) {
        float4 v = f[i];
        atomicAdd(o + i * 4 + 0, v.x);
        atomicAdd(o + i * 4 + 1, v.y);
        atomicAdd(o + i * 4 + 2, v.z);
        atomicAdd(o + i * 4 + 3, v.w);
    }
    if (COUNT && lane == 0) atomicAdd(&g_cnt[d], 1.0f);
}

__global__ void inv_kernel()
{
    int i = blockIdx.x * blockDim.x + threadIdx.x;
    if (i < N_NODES) g_inv[i] = 1.0f / fmaxf(g_cnt[i], 1.0f);
}

// ---------------------------------------------------------------------------
// Fused SAGE GEMM:  C[M,N] = act( (Aagg*inv) @ Wl  +  Xroot @ Wr  +  bias )
// Treated as [Aagg*inv | Xroot] (M x 2K)  @  [Wl ; Wr] (2K x N).
// BM=64, BN=64, BK=16, 256 threads, 4x4 per-thread micro-tile.
// ---------------------------------------------------------------------------
template<int K, int N, bool RELU>
__global__ __launch_bounds__(256)
void sage_gemm(const float* __restrict__ Aagg,
               const float* __restrict__ inv,
               const float* __restrict__ Xroot,
               const float* __restrict__ Wl,
               const float* __restrict__ Wr,
               const float* __restrict__ bias,
               float* __restrict__ Cout,
               int M)
{
    constexpr int BM = 64, BN = 64, BK = 16;
    __shared__ float As[BM][BK + 1];   // +1 pad vs bank conflicts
    __shared__ float Bs[BK][BN];

    int tid = threadIdx.x;
    int tx = tid & 15;        // N direction (x4)
    int ty = tid >> 4;        // M direction (x4)
    int m0 = blockIdx.x * BM;
    int n0 = blockIdx.y * BN;

    // A-tile load mapping: thread -> (row a_m, 4 consecutive k at a_k)
    int a_m = tid >> 2;
    int a_k = (tid & 3) * 4;
    // B-tile load mapping: thread -> (row b_r, 4 consecutive n at b_c)
    int b_r = tid >> 4;
    int b_c = (tid & 15) * 4;

    int  gm     = m0 + a_m;
    bool mvalid = gm < M;
    float scale_agg = mvalid ? inv[gm] : 0.0f;

    float acc[4][4] = {};

    for (int k0 = 0; k0 < 2 * K; k0 += BK) {
        bool first_half = (k0 < K);
        // ---- load A tile (with per-row mean scaling on the agg half) ----
        {
            const float* Abase = first_half ? Aagg : Xroot;
            int   kk  = first_half ? k0 : (k0 - K);
            float scl = first_half ? scale_agg : 1.0f;
            float4 av = mvalid
                ? *(const float4*)(Abase + (size_t)gm * K + kk + a_k)
                : make_float4(0.f, 0.f, 0.f, 0.f);
            As[a_m][a_k + 0] = av.x * scl;
            As[a_m][a_k + 1] = av.y * scl;
            As[a_m][a_k + 2] = av.z * scl;
            As[a_m][a_k + 3] = av.w * scl;
        }
        // ---- load B tile ----
        {
            const float* Bbase = first_half ? Wl : Wr;
            int br = first_half ? (k0 + b_r) : (k0 - K + b_r);
            float4 bv = *(const float4*)(Bbase + (size_t)br * N + n0 + b_c);
            *(float4*)&Bs[b_r][b_c] = bv;
        }
        __syncthreads();

        #pragma unroll
        for (int k = 0; k < BK; k++) {
            float a[4];
            #pragma unroll
            for (int i = 0; i < 4; i++) a[i] = As[ty * 4 + i][k];
            float4 bq = *(const float4*)&Bs[k][tx * 4];
            float b[4] = {bq.x, bq.y, bq.z, bq.w};
            #pragma unroll
            for (int i = 0; i < 4; i++)
                #pragma unroll
                for (int j = 0; j < 4; j++)
                    acc[i][j] += a[i] * b[j];
        }
        __syncthreads();
    }

    // ---- epilogue: + bias, optional relu, float4 store ----
    float4 bb = *(const float4*)(bias + n0 + tx * 4);
    #pragma unroll
    for (int i = 0; i < 4; i++) {
        int m = m0 + ty * 4 + i;
        if (m < M) {
            float4 o;
            o.x = acc[i][0] + bb.x;
            o.y = acc[i][1] + bb.y;
            o.z = acc[i][2] + bb.z;
            o.w = acc[i][3] + bb.w;
            if (RELU) {
                o.x = fmaxf(o.x, 0.f); o.y = fmaxf(o.y, 0.f);
                o.z = fmaxf(o.z, 0.f); o.w = fmaxf(o.w, 0.f);
            }
            *(float4*)(Cout + (size_t)m * N + n0 + tx * 4) = o;
        }
    }
}

// ---------------------------------------------------------------------------
// Launch
// ---------------------------------------------------------------------------
extern "C" void kernel_launch(void* const* d_in, const int* in_sizes, int n_in,
                              void* d_out, int out_size)
{
    const float* x   = (const float*)d_in[0];
    const int*   ei  = (const int*)d_in[1];     // int32 (JAX x64 disabled)
    const float* W1l = (const float*)d_in[2];
    const float* b1  = (const float*)d_in[3];
    const float* W1r = (const float*)d_in[4];
    const float* W2l = (const float*)d_in[5];
    const float* b2  = (const float*)d_in[6];
    const float* W2r = (const float*)d_in[7];
    float*       out = (float*)d_out;

    const int* src = ei;
    const int* dst = ei + N_EDGES;

    float *agg1, *agg2, *h, *cnt, *inv;
    cudaGetSymbolAddress((void**)&agg1, g_agg1);
    cudaGetSymbolAddress((void**)&agg2, g_agg2);
    cudaGetSymbolAddress((void**)&h,    g_h);
    cudaGetSymbolAddress((void**)&cnt,  g_cnt);
    cudaGetSymbolAddress((void**)&inv,  g_inv);

    // Zero accumulators (kernel nodes, not memset nodes)
    {
        int n4_1 = N_NODES * IN_C  / 4;
        int n4_2 = N_NODES * HID_C / 4;
        zero_kernel<<<1184, 256>>>((float4*)agg1, n4_1);
        zero_kernel<<<1184, 256>>>((float4*)agg2, n4_2);
        zero_kernel<<<64,   256>>>((float4*)cnt,  N_NODES / 4);  // 50000 % 4 == 0
    }

    // ---- layer 1 ----
    {
        int warps_per_block = 8;
        int grid = (N_EDGES + warps_per_block - 1) / warps_per_block;
        scatter_kernel<IN_C, true><<<grid, warps_per_block * 32>>>(x, src, dst, agg1);
    }
    inv_kernel<<<(N_NODES + 255) / 256, 256>>>();
    {
        dim3 grid((N_NODES + 63) / 64, HID_C / 64);
        sage_gemm<IN_C, HID_C, true><<<grid, 256>>>(agg1, inv, x, W1l, W1r, b1, h, N_NODES);
    }

    // ---- layer 2 ----
    {
        int warps_per_block = 8;
        int grid = (N_EDGES + warps_per_block - 1) / warps_per_block;
        scatter_kernel<HID_C, false><<<grid, warps_per_block * 32>>>(h, src, dst, agg2);
    }
    {
        dim3 grid((N_NODES + 63) / 64, OUT_C / 64);
        sage_gemm<HID_C, OUT_C, false><<<grid, 256>>>(agg2, inv, h, W2l, W2r, b2, out, N_NODES);
    }
}

// round 4
// speedup vs baseline: 1.6941x; 1.6941x over previous
#include <cuda_runtime.h>
#include <cuda_bf16.h>
#include <cstdint>

// Problem constants (match reference_code)
#define IN_C    128
#define HID_C   256
#define OUT_C   128
#define N_NODES 50000
#define N_EDGES 600000

// ---------------------------------------------------------------------------
// Scratch (no cudaMalloc allowed): device globals
// ---------------------------------------------------------------------------
__device__ float g_agg1[(size_t)N_NODES * IN_C];   // 25.6 MB  mean-sum of x
__device__ float g_agg2[(size_t)N_NODES * HID_C];  // 51.2 MB  mean-sum of h
__device__ float g_h   [(size_t)N_NODES * HID_C];  // 51.2 MB  layer-1 output
__device__ float g_inv [N_NODES];                  // 1 / max(deg, 1)

__device__ int g_cnt_int  [N_NODES];               // in-degree histogram
__device__ int g_row_start[N_NODES + 1];           // CSR row offsets (by dst)
__device__ int g_cursor   [N_NODES];               // fill cursors
__device__ int g_csr_src  [N_EDGES];               // CSR column (src) indices

// ---------------------------------------------------------------------------
// CSR build
// ---------------------------------------------------------------------------
__global__ void zero_int_kernel(int* __restrict__ p, int n)
{
    int i = blockIdx.x * blockDim.x + threadIdx.x;
    if (i < n) p[i] = 0;
}

__global__ void hist_kernel(const int* __restrict__ dst)
{
    int e = blockIdx.x * blockDim.x + threadIdx.x;
    if (e < N_EDGES) atomicAdd(&g_cnt_int[dst[e]], 1);
}

// Single-block exclusive scan of g_cnt_int -> g_row_start (N_NODES entries + total)
__global__ void scan_kernel()
{
    __shared__ int sdata[1024];
    __shared__ int soffset;
    int tid = threadIdx.x;
    if (tid == 0) soffset = 0;
    __syncthreads();
    for (int base = 0; base < N_NODES; base += 1024) {
        int i = base + tid;
        int v = (i < N_NODES) ? g_cnt_int[i] : 0;
        sdata[tid] = v;
        __syncthreads();
        #pragma unroll
        for (int s = 1; s < 1024; s <<= 1) {
            int t = (tid >= s) ? sdata[tid - s] : 0;
            __syncthreads();
            sdata[tid] += t;
            __syncthreads();
        }
        int incl = sdata[tid];
        if (i < N_NODES) g_row_start[i] = soffset + (incl - v);
        int chunk_total = sdata[1023];
        __syncthreads();
        if (tid == 0) soffset += chunk_total;
        __syncthreads();
    }
    if (tid == 0) g_row_start[N_NODES] = soffset;
}

__global__ void init_cursor_inv_kernel()
{
    int i = blockIdx.x * blockDim.x + threadIdx.x;
    if (i < N_NODES) {
        g_cursor[i] = g_row_start[i];
        g_inv[i] = 1.0f / fmaxf((float)g_cnt_int[i], 1.0f);
    }
}

__global__ void fill_kernel(const int* __restrict__ src, const int* __restrict__ dst)
{
    int e = blockIdx.x * blockDim.x + threadIdx.x;
    if (e < N_EDGES) {
        int pos = atomicAdd(&g_cursor[dst[e]], 1);
        g_csr_src[pos] = src[e];
    }
}

// ---------------------------------------------------------------------------
// Gather-aggregate: one warp per node, register float4 accumulators.
// agg[n] = sum over in-neighbors s of feat[s]   (mean applied later via g_inv)
// ---------------------------------------------------------------------------
template<int C>
__global__ void gather_kernel(const float* __restrict__ feat,
                              float* __restrict__ agg)
{
    int node = blockIdx.x * (blockDim.x >> 5) + (threadIdx.x >> 5);
    if (node >= N_NODES) return;
    int lane = threadIdx.x & 31;
    int beg = g_row_start[node];
    int end = g_row_start[node + 1];

    constexpr int V = C / 128;            // float4 chunks per lane (1 or 2)
    float4 acc[V];
    #pragma unroll
    for (int v = 0; v < V; v++) acc[v] = make_float4(0.f, 0.f, 0.f, 0.f);

    for (int k = beg; k < end; k++) {
        int s = g_csr_src[k];             // uniform per warp (broadcast load)
        const float4* f = (const float4*)(feat + (size_t)s * C);
        #pragma unroll
        for (int v = 0; v < V; v++) {
            float4 val = f[lane + 32 * v];
            acc[v].x += val.x; acc[v].y += val.y;
            acc[v].z += val.z; acc[v].w += val.w;
        }
    }
    float4* o = (float4*)(agg + (size_t)node * C);
    #pragma unroll
    for (int v = 0; v < V; v++) o[lane + 32 * v] = acc[v];
}

// ---------------------------------------------------------------------------
// Fused SAGE GEMM:  C[M,N] = act( (Aagg*inv) @ Wl  +  Xroot @ Wr  +  bias )
// Treated as [Aagg*inv | Xroot] (M x 2K)  @  [Wl ; Wr] (2K x N).
// BM=64, BN=64, BK=16, 256 threads, 4x4 per-thread micro-tile.
// ---------------------------------------------------------------------------
template<int K, int N, bool RELU>
__global__ __launch_bounds__(256)
void sage_gemm(const float* __restrict__ Aagg,
               const float* __restrict__ inv,
               const float* __restrict__ Xroot,
               const float* __restrict__ Wl,
               const float* __restrict__ Wr,
               const float* __restrict__ bias,
               float* __restrict__ Cout,
               int M)
{
    constexpr int BM = 64, BN = 64, BK = 16;
    __shared__ float As[BM][BK + 1];
    __shared__ float Bs[BK][BN];

    int tid = threadIdx.x;
    int tx = tid & 15;        // N direction (x4)
    int ty = tid >> 4;        // M direction (x4)
    int m0 = blockIdx.x * BM;
    int n0 = blockIdx.y * BN;

    int a_m = tid >> 2;
    int a_k = (tid & 3) * 4;
    int b_r = tid >> 4;
    int b_c = (tid & 15) * 4;

    int  gm     = m0 + a_m;
    bool mvalid = gm < M;
    float scale_agg = mvalid ? inv[gm] : 0.0f;

    float acc[4][4] = {};

    for (int k0 = 0; k0 < 2 * K; k0 += BK) {
        bool first_half = (k0 < K);
        {
            const float* Abase = first_half ? Aagg : Xroot;
            int   kk  = first_half ? k0 : (k0 - K);
            float scl = first_half ? scale_agg : 1.0f;
            float4 av = mvalid
                ? *(const float4*)(Abase + (size_t)gm * K + kk + a_k)
                : make_float4(0.f, 0.f, 0.f, 0.f);
            As[a_m][a_k + 0] = av.x * scl;
            As[a_m][a_k + 1] = av.y * scl;
            As[a_m][a_k + 2] = av.z * scl;
            As[a_m][a_k + 3] = av.w * scl;
        }
        {
            const float* Bbase = first_half ? Wl : Wr;
            int br = first_half ? (k0 + b_r) : (k0 - K + b_r);
            float4 bv = *(const float4*)(Bbase + (size_t)br * N + n0 + b_c);
            *(float4*)&Bs[b_r][b_c] = bv;
        }
        __syncthreads();

        #pragma unroll
        for (int k = 0; k < BK; k++) {
            float a[4];
            #pragma unroll
            for (int i = 0; i < 4; i++) a[i] = As[ty * 4 + i][k];
            float4 bq = *(const float4*)&Bs[k][tx * 4];
            float b[4] = {bq.x, bq.y, bq.z, bq.w};
            #pragma unroll
            for (int i = 0; i < 4; i++)
                #pragma unroll
                for (int j = 0; j < 4; j++)
                    acc[i][j] += a[i] * b[j];
        }
        __syncthreads();
    }

    float4 bb = *(const float4*)(bias + n0 + tx * 4);
    #pragma unroll
    for (int i = 0; i < 4; i++) {
        int m = m0 + ty * 4 + i;
        if (m < M) {
            float4 o;
            o.x = acc[i][0] + bb.x;
            o.y = acc[i][1] + bb.y;
            o.z = acc[i][2] + bb.z;
            o.w = acc[i][3] + bb.w;
            if (RELU) {
                o.x = fmaxf(o.x, 0.f); o.y = fmaxf(o.y, 0.f);
                o.z = fmaxf(o.z, 0.f); o.w = fmaxf(o.w, 0.f);
            }
            *(float4*)(Cout + (size_t)m * N + n0 + tx * 4) = o;
        }
    }
}

// ---------------------------------------------------------------------------
// Launch
// ---------------------------------------------------------------------------
extern "C" void kernel_launch(void* const* d_in, const int* in_sizes, int n_in,
                              void* d_out, int out_size)
{
    const float* x   = (const float*)d_in[0];
    const int*   ei  = (const int*)d_in[1];     // int32 (JAX x64 disabled)
    const float* W1l = (const float*)d_in[2];
    const float* b1  = (const float*)d_in[3];
    const float* W1r = (const float*)d_in[4];
    const float* W2l = (const float*)d_in[5];
    const float* b2  = (const float*)d_in[6];
    const float* W2r = (const float*)d_in[7];
    float*       out = (float*)d_out;

    const int* src = ei;
    const int* dst = ei + N_EDGES;

    float *agg1, *agg2, *h, *inv;
    int *cnt_int;
    cudaGetSymbolAddress((void**)&agg1,    g_agg1);
    cudaGetSymbolAddress((void**)&agg2,    g_agg2);
    cudaGetSymbolAddress((void**)&h,       g_h);
    cudaGetSymbolAddress((void**)&inv,     g_inv);
    cudaGetSymbolAddress((void**)&cnt_int, g_cnt_int);

    // ---- CSR build (shared by both layers) ----
    zero_int_kernel<<<(N_NODES + 255) / 256, 256>>>(cnt_int, N_NODES);
    hist_kernel<<<(N_EDGES + 255) / 256, 256>>>(dst);
    scan_kernel<<<1, 1024>>>();
    init_cursor_inv_kernel<<<(N_NODES + 255) / 256, 256>>>();
    fill_kernel<<<(N_EDGES + 255) / 256, 256>>>(src, dst);

    // ---- layer 1 ----
    {
        int warps_per_block = 8;
        int grid = (N_NODES + warps_per_block - 1) / warps_per_block;
        gather_kernel<IN_C><<<grid, warps_per_block * 32>>>(x, agg1);
    }
    {
        dim3 grid((N_NODES + 63) / 64, HID_C / 64);
        sage_gemm<IN_C, HID_C, true><<<grid, 256>>>(agg1, inv, x, W1l, W1r, b1, h, N_NODES);
    }

    // ---- layer 2 ----
    {
        int warps_per_block = 8;
        int grid = (N_NODES + warps_per_block - 1) / warps_per_block;
        gather_kernel<HID_C><<<grid, warps_per_block * 32>>>(h, agg2);
    }
    {
        dim3 grid((N_NODES + 63) / 64, OUT_C / 64);
        sage_gemm<HID_C, OUT_C, false><<<grid, 256>>>(agg2, inv, h, W2l, W2r, b2, out, N_NODES);
    }
}